// round 12
// baseline (speedup 1.0000x reference)
#include <cuda_runtime.h>
#include <cuda_fp16.h>
#include <cstdint>

#define N_NODES  10000
#define N_EDGES  320000
#define IN_DIM   256
#define HIDDEN   256
#define OUT_DIM  128
#define CAP      96     // per-node bucket capacity; max degree ~56 (11σ margin)

// ---------------- device scratch (static) ----------------
// g_cnt starts zero (static init); spmm2 re-zeroes it each invocation.
__device__ int    g_cnt[N_NODES];
__device__ int2   g_bucket[N_NODES * CAP];                  // {src, float bits of val}
__device__ __align__(16) __half g_Y0h[N_NODES * HIDDEN];    // fp16(X @ W0)
__device__ float4 g_H [N_NODES * HIDDEN / 4];               // relu(A @ Y0), fp32
__device__ __align__(16) __half g_Y1h[N_NODES * OUT_DIM];   // fp16(H @ W1)

// ---------------- bucket scatter ----------------
__global__ void scatter_kernel(const void* __restrict__ src,
                               const void* __restrict__ dst,
                               const float* __restrict__ val) {
    __shared__ int sh_is64;
    int tid = threadIdx.x;
    if (tid < 32) {
        const int* w = (const int*)src;
        int bad = (w[2 * tid + 1] != 0) || (w[2 * (tid + 32) + 1] != 0);
        int all_zero = __all_sync(0xFFFFFFFFu, !bad);
        if (tid == 0) sh_is64 = all_zero;
    }
    __syncthreads();
    int is64 = sh_is64;

    int e = blockIdx.x * blockDim.x + tid;
    if (e < N_EDGES) {
        int d, s;
        if (is64) {
            d = (int)((const long long*)dst)[e];
            s = (int)((const long long*)src)[e];
        } else {
            d = ((const int*)dst)[e];
            s = ((const int*)src)[e];
        }
        int pos = atomicAdd(&g_cnt[d], 1);
        if (pos < CAP)
            g_bucket[d * CAP + pos] = make_int2(s, __float_as_int(val[e]));
    }
}

// ---------------- tf32 MMA helpers (proven R5-R9) ----------------
__device__ __forceinline__ uint32_t f2tf32(float x) {
    uint32_t r;
    asm("cvt.rna.tf32.f32 %0, %1;" : "=r"(r) : "f"(x));
    return r;
}

__device__ __forceinline__ void mma_tf32(float* d, const uint32_t* a,
                                         const uint32_t* b, const float* c) {
    asm("mma.sync.aligned.m16n8k8.row.col.f32.tf32.tf32.f32 "
        "{%0,%1,%2,%3},{%4,%5,%6,%7},{%8,%9},{%10,%11,%12,%13};"
        : "=f"(d[0]), "=f"(d[1]), "=f"(d[2]), "=f"(d[3])
        : "r"(a[0]), "r"(a[1]), "r"(a[2]), "r"(a[3]),
          "r"(b[0]), "r"(b[1]),
          "f"(c[0]), "f"(c[1]), "f"(c[2]), "f"(c[3]));
}

// ---------------- tf32 GEMM, fp16 out: BM=32, BN=64, BK=32, 128 thr ----------------
// 4 warps as 1m x 4n; warp tile 32(m) x 16(n); reg-staged double buffer.
// As[m][k] stride 36, Bs[k][n] stride 72 (R9-proven conflict-free layout).
__device__ __forceinline__ void gemm_tf32_body(const float* __restrict__ A,
                                               const float* __restrict__ B,
                                               __half* __restrict__ C,
                                               int M, int N) {
    const int SA = 36;
    const int SB = 72;
    __shared__ __align__(16) uint32_t As[2][32 * SA];
    __shared__ __align__(16) uint32_t Bs[2][32 * SB];

    int tid  = threadIdx.x;
    int lane = tid & 31;
    int wid  = tid >> 5;          // 0..3
    int wn = wid * 16;            // warp n-offset
    int bm = blockIdx.y * 32;
    int bn = blockIdx.x * 64;

    // A tile: 32x32 fp32 -> 2 float4/thread
    int a_kf = tid & 7;           // k float4 index (k = 4*a_kf)
    int a_m0 = tid >> 3;          // 0..15, rows m0, m0+16
    // B tile: 32x64 fp32 -> 4 float4/thread
    int b_nq = tid & 15;          // n float4 index
    int b_k0 = tid >> 4;          // 0..7, k rows k0 + it*8

    float acc[2][2][4] = {};
    float4 ar[2], br[4];

    // prologue: load tile 0
    #pragma unroll
    for (int it = 0; it < 2; it++) {
        int gr = bm + a_m0 + it * 16;
        ar[it] = (gr < M) ? *(const float4*)&A[(size_t)gr * 256 + a_kf * 4]
                          : make_float4(0.f, 0.f, 0.f, 0.f);
    }
    #pragma unroll
    for (int it = 0; it < 4; it++)
        br[it] = *(const float4*)&B[(size_t)(b_k0 + it * 8) * N + bn + b_nq * 4];

    #pragma unroll
    for (int k0 = 0; k0 < 8; k0++) {
        int cur = k0 & 1;
        // stage regs -> smem[cur] (convert to tf32)
        #pragma unroll
        for (int it = 0; it < 2; it++) {
            int m = a_m0 + it * 16;
            *(uint4*)&As[cur][m * SA + a_kf * 4] =
                make_uint4(f2tf32(ar[it].x), f2tf32(ar[it].y),
                           f2tf32(ar[it].z), f2tf32(ar[it].w));
        }
        #pragma unroll
        for (int it = 0; it < 4; it++) {
            int k = b_k0 + it * 8;
            *(uint4*)&Bs[cur][k * SB + b_nq * 4] =
                make_uint4(f2tf32(br[it].x), f2tf32(br[it].y),
                           f2tf32(br[it].z), f2tf32(br[it].w));
        }
        __syncthreads();

        // prefetch next tile (overlaps MMA below)
        if (k0 < 7) {
            int kb = (k0 + 1) * 32;
            #pragma unroll
            for (int it = 0; it < 2; it++) {
                int gr = bm + a_m0 + it * 16;
                ar[it] = (gr < M) ? *(const float4*)&A[(size_t)gr * 256 + kb + a_kf * 4]
                                  : make_float4(0.f, 0.f, 0.f, 0.f);
            }
            #pragma unroll
            for (int it = 0; it < 4; it++)
                br[it] = *(const float4*)&B[(size_t)(kb + b_k0 + it * 8) * N + bn + b_nq * 4];
        }

        // compute: 4 x k8 steps (R9-verbatim fragment indexing)
        #pragma unroll
        for (int ks = 0; ks < 4; ks++) {
            int kk = ks * 8;
            uint32_t bf[2][2];
            #pragma unroll
            for (int nf = 0; nf < 2; nf++) {
                int n = wn + nf * 8 + (lane >> 2);
                bf[nf][0] = Bs[cur][(kk + (lane & 3)) * SB + n];
                bf[nf][1] = Bs[cur][(kk + 4 + (lane & 3)) * SB + n];
            }
            #pragma unroll
            for (int mf = 0; mf < 2; mf++) {
                int m = mf * 16 + (lane >> 2);
                uint32_t af[4];
                af[0] = As[cur][m * SA + kk + (lane & 3)];
                af[1] = As[cur][(m + 8) * SA + kk + (lane & 3)];
                af[2] = As[cur][m * SA + kk + 4 + (lane & 3)];
                af[3] = As[cur][(m + 8) * SA + kk + 4 + (lane & 3)];
                #pragma unroll
                for (int nf = 0; nf < 2; nf++)
                    mma_tf32(acc[mf][nf], af, bf[nf], acc[mf][nf]);
            }
        }
        __syncthreads();
    }

    // epilogue: fp32 acc -> fp16 pairs (R8-proven mapping)
    #pragma unroll
    for (int mf = 0; mf < 2; mf++) {
        int r0 = bm + mf * 16 + (lane >> 2);
        #pragma unroll
        for (int nf = 0; nf < 2; nf++) {
            int c0 = bn + wn + nf * 8 + 2 * (lane & 3);
            if (r0 < M)
                *(__half2*)&C[(size_t)r0 * N + c0] =
                    __floats2half2_rn(acc[mf][nf][0], acc[mf][nf][1]);
            if (r0 + 8 < M)
                *(__half2*)&C[(size_t)(r0 + 8) * N + c0] =
                    __floats2half2_rn(acc[mf][nf][2], acc[mf][nf][3]);
        }
    }
}

__global__ __launch_bounds__(128) void gemm_XW0_kernel(const float* __restrict__ A,
                                                       const float* __restrict__ B, int M) {
    gemm_tf32_body(A, B, g_Y0h, M, HIDDEN);
}

__global__ __launch_bounds__(128) void gemm_HW1_kernel(const float* __restrict__ B, int M) {
    gemm_tf32_body((const float*)g_H, B, g_Y1h, M, OUT_DIM);
}

// ---------------- bucket SpMMs (R8-proven, warp per row, 2-edge unroll) ----------------
__device__ __forceinline__ void fma_h8(float* a, uint4 r, float v) {
    float2 f0 = __half22float2(*(__half2*)&r.x);
    float2 f1 = __half22float2(*(__half2*)&r.y);
    float2 f2 = __half22float2(*(__half2*)&r.z);
    float2 f3 = __half22float2(*(__half2*)&r.w);
    a[0] = fmaf(v, f0.x, a[0]); a[1] = fmaf(v, f0.y, a[1]);
    a[2] = fmaf(v, f1.x, a[2]); a[3] = fmaf(v, f1.y, a[3]);
    a[4] = fmaf(v, f2.x, a[4]); a[5] = fmaf(v, f2.y, a[5]);
    a[6] = fmaf(v, f3.x, a[6]); a[7] = fmaf(v, f3.y, a[7]);
}

// g_H = relu(A @ Y0h): each lane covers cols [lane*8, lane*8+8), fp32 out
__global__ void spmm1_kernel() {
    int row = blockIdx.x * (blockDim.x >> 5) + (threadIdx.x >> 5);
    if (row >= N_NODES) return;
    int lane = threadIdx.x & 31;
    int deg = g_cnt[row];
    if (deg > CAP) deg = CAP;
    const int2* bk = g_bucket + row * CAP;

    float acc[8] = {};
    int e = 0;
    for (; e + 2 <= deg; e += 2) {
        int2 t0 = bk[e], t1 = bk[e + 1];
        uint4 r0 = *(const uint4*)(g_Y0h + (size_t)t0.x * HIDDEN + lane * 8);
        uint4 r1 = *(const uint4*)(g_Y0h + (size_t)t1.x * HIDDEN + lane * 8);
        fma_h8(acc, r0, __int_as_float(t0.y));
        fma_h8(acc, r1, __int_as_float(t1.y));
    }
    if (e < deg) {
        int2 t0 = bk[e];
        uint4 r0 = *(const uint4*)(g_Y0h + (size_t)t0.x * HIDDEN + lane * 8);
        fma_h8(acc, r0, __int_as_float(t0.y));
    }

    #pragma unroll
    for (int i = 0; i < 8; i++) acc[i] = fmaxf(acc[i], 0.f);
    g_H[(size_t)row * 64 + lane * 2]     = make_float4(acc[0], acc[1], acc[2], acc[3]);
    g_H[(size_t)row * 64 + lane * 2 + 1] = make_float4(acc[4], acc[5], acc[6], acc[7]);
}

// out = A @ Y1h: each lane covers cols [lane*4, lane*4+4). Zero-restores g_cnt.
__global__ void spmm2_kernel(float4* __restrict__ out) {
    int row = blockIdx.x * (blockDim.x >> 5) + (threadIdx.x >> 5);
    if (row >= N_NODES) return;
    int lane = threadIdx.x & 31;
    int deg = g_cnt[row];
    if (deg > CAP) deg = CAP;
    const int2* bk = g_bucket + row * CAP;

    float acc[4] = {};
    int e = 0;
    for (; e + 2 <= deg; e += 2) {
        int2 t0 = bk[e], t1 = bk[e + 1];
        uint2 r0 = *(const uint2*)(g_Y1h + (size_t)t0.x * OUT_DIM + lane * 4);
        uint2 r1 = *(const uint2*)(g_Y1h + (size_t)t1.x * OUT_DIM + lane * 4);
        float v0 = __int_as_float(t0.y), v1 = __int_as_float(t1.y);
        float2 a0 = __half22float2(*(__half2*)&r0.x);
        float2 a1 = __half22float2(*(__half2*)&r0.y);
        float2 b0 = __half22float2(*(__half2*)&r1.x);
        float2 b1 = __half22float2(*(__half2*)&r1.y);
        acc[0] = fmaf(v0, a0.x, acc[0]); acc[1] = fmaf(v0, a0.y, acc[1]);
        acc[2] = fmaf(v0, a1.x, acc[2]); acc[3] = fmaf(v0, a1.y, acc[3]);
        acc[0] = fmaf(v1, b0.x, acc[0]); acc[1] = fmaf(v1, b0.y, acc[1]);
        acc[2] = fmaf(v1, b1.x, acc[2]); acc[3] = fmaf(v1, b1.y, acc[3]);
    }
    if (e < deg) {
        int2 t0 = bk[e];
        uint2 r0 = *(const uint2*)(g_Y1h + (size_t)t0.x * OUT_DIM + lane * 4);
        float v0 = __int_as_float(t0.y);
        float2 a0 = __half22float2(*(__half2*)&r0.x);
        float2 a1 = __half22float2(*(__half2*)&r0.y);
        acc[0] = fmaf(v0, a0.x, acc[0]); acc[1] = fmaf(v0, a0.y, acc[1]);
        acc[2] = fmaf(v0, a1.x, acc[2]); acc[3] = fmaf(v0, a1.y, acc[3]);
    }
    out[(size_t)row * 32 + lane] = make_float4(acc[0], acc[1], acc[2], acc[3]);

    if (lane == 0) g_cnt[row] = 0;   // restore invariant for next invocation
}

// ---------------- launch ----------------
extern "C" void kernel_launch(void* const* d_in, const int* in_sizes, int n_in,
                              void* d_out, int out_size) {
    const float* features = (const float*)d_in[0];
    const void*  edge_src = d_in[1];
    const void*  edge_dst = d_in[2];
    const float* edge_val = (const float*)d_in[3];
    const float* W0       = (const float*)d_in[4];
    const float* W1       = (const float*)d_in[5];
    float4*      out      = (float4*)d_out;

    static cudaStream_t s_side = nullptr;
    static cudaEvent_t  ev_fork = nullptr, ev_join = nullptr;
    if (s_side == nullptr) {
        cudaStreamCreateWithFlags(&s_side, cudaStreamNonBlocking);
        cudaEventCreateWithFlags(&ev_fork, cudaEventDisableTiming);
        cudaEventCreateWithFlags(&ev_join, cudaEventDisableTiming);
    }

    // Fork: GEMM1 on side branch (independent of edge bucketing)
    cudaEventRecord(ev_fork, 0);
    cudaStreamWaitEvent(s_side, ev_fork, 0);
    {
        dim3 grid(HIDDEN / 64, (N_NODES + 31) / 32);
        gemm_XW0_kernel<<<grid, 128, 0, s_side>>>(features, W0, N_NODES);
    }
    cudaEventRecord(ev_join, s_side);

    // Main branch: bucket the edges
    scatter_kernel<<<(N_EDGES + 255) / 256, 256>>>(edge_src, edge_dst, edge_val);

    // Join: SpMM1 needs both buckets and Y0h
    cudaStreamWaitEvent(0, ev_join, 0);

    // g_H = relu(A @ Y0h)  (fp32)
    spmm1_kernel<<<(N_NODES + 7) / 8, 256>>>();

    // Y1h = H @ W1
    {
        dim3 grid(OUT_DIM / 64, (N_NODES + 31) / 32);
        gemm_HW1_kernel<<<grid, 128>>>(W1, N_NODES);
    }

    // out = A @ Y1h  (also zero-restores g_cnt)
    spmm2_kernel<<<(N_NODES + 7) / 8, 256>>>(out);
}

// round 13
// speedup vs baseline: 1.0880x; 1.0880x over previous
#include <cuda_runtime.h>
#include <cuda_fp16.h>
#include <cstdint>

#define N_NODES  10000
#define N_EDGES  320000
#define IN_DIM   256
#define HIDDEN   256
#define OUT_DIM  128
#define CAP      96     // per-node bucket capacity; max degree ~56 (11σ margin)

// ---------------- device scratch (static) ----------------
// g_cnt starts zero (static init); spmm2 re-zeroes it each invocation.
__device__ int    g_cnt[N_NODES];
__device__ int2   g_bucket[N_NODES * CAP];                  // {src, float bits of val}
__device__ __align__(16) __half g_Y0h[N_NODES * HIDDEN];    // fp16(X @ W0)
__device__ __align__(16) __half g_Hh [N_NODES * HIDDEN];    // fp16 relu(A @ Y0)
__device__ __align__(16) __half g_Y1h[N_NODES * OUT_DIM];   // fp16(H @ W1)

// ---------------- bucket scatter (R7-proven) ----------------
__global__ void scatter_kernel(const void* __restrict__ src,
                               const void* __restrict__ dst,
                               const float* __restrict__ val) {
    __shared__ int sh_is64;
    int tid = threadIdx.x;
    if (tid < 32) {
        const int* w = (const int*)src;
        int bad = (w[2 * tid + 1] != 0) || (w[2 * (tid + 32) + 1] != 0);
        int all_zero = __all_sync(0xFFFFFFFFu, !bad);
        if (tid == 0) sh_is64 = all_zero;
    }
    __syncthreads();
    int is64 = sh_is64;

    int e = blockIdx.x * blockDim.x + tid;
    if (e < N_EDGES) {
        int d, s;
        if (is64) {
            d = (int)((const long long*)dst)[e];
            s = (int)((const long long*)src)[e];
        } else {
            d = ((const int*)dst)[e];
            s = ((const int*)src)[e];
        }
        int pos = atomicAdd(&g_cnt[d], 1);
        if (pos < CAP)
            g_bucket[d * CAP + pos] = make_int2(s, __float_as_int(val[e]));
    }
}

// ---------------- tf32 MMA helpers (R5-R9 proven) ----------------
__device__ __forceinline__ uint32_t f2tf32(float x) {
    uint32_t r;
    asm("cvt.rna.tf32.f32 %0, %1;" : "=r"(r) : "f"(x));
    return r;
}

__device__ __forceinline__ void mma_tf32(float* d, const uint32_t* a,
                                         const uint32_t* b, const float* c) {
    asm("mma.sync.aligned.m16n8k8.row.col.f32.tf32.tf32.f32 "
        "{%0,%1,%2,%3},{%4,%5,%6,%7},{%8,%9},{%10,%11,%12,%13};"
        : "=f"(d[0]), "=f"(d[1]), "=f"(d[2]), "=f"(d[3])
        : "r"(a[0]), "r"(a[1]), "r"(a[2]), "r"(a[3]),
          "r"(b[0]), "r"(b[1]),
          "f"(c[0]), "f"(c[1]), "f"(c[2]), "f"(c[3]));
}

#define SA 36   // As[m][k] stride (uint32)
#define SB 72   // Bs[k][n] stride (uint32)

// R9-verbatim compute: 4 warps 2m x 2n, warp tile 32x32, BK=32 (4 x k8 steps)
__device__ __forceinline__ void gemm_compute(const uint32_t* As1, const uint32_t* Bs1,
                                             int wm, int wn, int lane,
                                             float acc[2][4][4]) {
    #pragma unroll
    for (int ks = 0; ks < 4; ks++) {
        int kk = ks * 8;
        uint32_t bf[4][2];
        #pragma unroll
        for (int nf = 0; nf < 4; nf++) {
            int n = wn + nf * 8 + (lane >> 2);
            bf[nf][0] = Bs1[(kk + (lane & 3)) * SB + n];
            bf[nf][1] = Bs1[(kk + 4 + (lane & 3)) * SB + n];
        }
        #pragma unroll
        for (int mf = 0; mf < 2; mf++) {
            int m = wm + mf * 16 + (lane >> 2);
            uint32_t af[4];
            af[0] = As1[m * SA + kk + (lane & 3)];
            af[1] = As1[(m + 8) * SA + kk + (lane & 3)];
            af[2] = As1[m * SA + kk + 4 + (lane & 3)];
            af[3] = As1[(m + 8) * SA + kk + 4 + (lane & 3)];
            #pragma unroll
            for (int nf = 0; nf < 4; nf++)
                mma_tf32(acc[mf][nf], af, bf[nf], acc[mf][nf]);
        }
    }
}

// R9-verbatim epilogue: fp32 acc -> fp16 pairs into C[M][N]
__device__ __forceinline__ void gemm_epilogue(__half* __restrict__ C, int M, int N,
                                              int bm, int bn, int wm, int wn,
                                              int lane, float acc[2][4][4]) {
    #pragma unroll
    for (int mf = 0; mf < 2; mf++) {
        int r0 = bm + wm + mf * 16 + (lane >> 2);
        #pragma unroll
        for (int nf = 0; nf < 4; nf++) {
            int c0 = bn + wn + nf * 8 + 2 * (lane & 3);
            if (r0 < M)
                *(__half2*)&C[(size_t)r0 * N + c0] =
                    __floats2half2_rn(acc[mf][nf][0], acc[mf][nf][1]);
            if (r0 + 8 < M)
                *(__half2*)&C[(size_t)(r0 + 8) * N + c0] =
                    __floats2half2_rn(acc[mf][nf][2], acc[mf][nf][3]);
        }
    }
}

// GEMM1 (R9-verbatim): A fp32 [M][256], B fp32 [256][N] -> C fp16
// BM=64, BN=64, BK=32, 128 threads, reg-staged double buffer.
__global__ __launch_bounds__(128) void gemm_XW0_kernel(const float* __restrict__ A,
                                                       const float* __restrict__ B, int M) {
    const int N = HIDDEN;
    __shared__ __align__(16) uint32_t As[2][64 * SA];
    __shared__ __align__(16) uint32_t Bs[2][32 * SB];

    int tid  = threadIdx.x;
    int lane = tid & 31;
    int wid  = tid >> 5;
    int wm = (wid & 1) * 32;
    int wn = (wid >> 1) * 32;
    int bm = blockIdx.y * 64;
    int bn = blockIdx.x * 64;

    int a_kf = tid & 7;
    int a_m0 = tid >> 3;
    int b_nq = tid & 15;
    int b_k0 = tid >> 4;

    float acc[2][4][4] = {};
    float4 ar[4], br[4];

    #pragma unroll
    for (int it = 0; it < 4; it++) {
        int gr = bm + a_m0 + it * 16;
        ar[it] = (gr < M) ? *(const float4*)&A[(size_t)gr * 256 + a_kf * 4]
                          : make_float4(0.f, 0.f, 0.f, 0.f);
        br[it] = *(const float4*)&B[(size_t)(b_k0 + it * 8) * N + bn + b_nq * 4];
    }

    #pragma unroll
    for (int k0 = 0; k0 < 8; k0++) {
        int cur = k0 & 1;
        #pragma unroll
        for (int it = 0; it < 4; it++) {
            int m = a_m0 + it * 16;
            *(uint4*)&As[cur][m * SA + a_kf * 4] =
                make_uint4(f2tf32(ar[it].x), f2tf32(ar[it].y),
                           f2tf32(ar[it].z), f2tf32(ar[it].w));
            int k = b_k0 + it * 8;
            *(uint4*)&Bs[cur][k * SB + b_nq * 4] =
                make_uint4(f2tf32(br[it].x), f2tf32(br[it].y),
                           f2tf32(br[it].z), f2tf32(br[it].w));
        }
        __syncthreads();

        if (k0 < 7) {
            int kb = (k0 + 1) * 32;
            #pragma unroll
            for (int it = 0; it < 4; it++) {
                int gr = bm + a_m0 + it * 16;
                ar[it] = (gr < M) ? *(const float4*)&A[(size_t)gr * 256 + kb + a_kf * 4]
                                  : make_float4(0.f, 0.f, 0.f, 0.f);
                br[it] = *(const float4*)&B[(size_t)(kb + b_k0 + it * 8) * N + bn + b_nq * 4];
            }
        }

        gemm_compute(As[cur], Bs[cur], wm, wn, lane, acc);
        __syncthreads();
    }

    gemm_epilogue(g_Y0h, M, N, bm, bn, wm, wn, lane, acc);
}

// GEMM2: A fp16 (g_Hh) [M][256], B fp32 [256][N] -> C fp16
// Identical structure; only A staging differs (uint4 = 8 halves -> tf32).
__global__ __launch_bounds__(128) void gemm_HW1_kernel(const float* __restrict__ B, int M) {
    const int N = OUT_DIM;
    __shared__ __align__(16) uint32_t As[2][64 * SA];
    __shared__ __align__(16) uint32_t Bs[2][32 * SB];

    int tid  = threadIdx.x;
    int lane = tid & 31;
    int wid  = tid >> 5;
    int wm = (wid & 1) * 32;
    int wn = (wid >> 1) * 32;
    int bm = blockIdx.y * 64;
    int bn = blockIdx.x * 64;

    // A tile: 64 rows x 32 halves; 128 threads -> 2 uint4 (8 halves) each
    int a_kf = tid & 3;       // k uint4 index (k = 8*a_kf)
    int a_m0 = tid >> 2;      // 0..31, rows m0, m0+32
    int b_nq = tid & 15;
    int b_k0 = tid >> 4;

    float acc[2][4][4] = {};
    uint4  ar[2];
    float4 br[4];

    #pragma unroll
    for (int it = 0; it < 2; it++) {
        int gr = bm + a_m0 + it * 32;
        ar[it] = (gr < M) ? *(const uint4*)&g_Hh[(size_t)gr * 256 + a_kf * 8]
                          : make_uint4(0, 0, 0, 0);
    }
    #pragma unroll
    for (int it = 0; it < 4; it++)
        br[it] = *(const float4*)&B[(size_t)(b_k0 + it * 8) * N + bn + b_nq * 4];

    #pragma unroll
    for (int k0 = 0; k0 < 8; k0++) {
        int cur = k0 & 1;
        // stage A: 8 halves -> 8 tf32 words
        #pragma unroll
        for (int it = 0; it < 2; it++) {
            int m = a_m0 + it * 32;
            const __half2* hp = (const __half2*)&ar[it];
            float2 f0 = __half22float2(hp[0]);
            float2 f1 = __half22float2(hp[1]);
            float2 f2 = __half22float2(hp[2]);
            float2 f3 = __half22float2(hp[3]);
            *(uint4*)&As[cur][m * SA + a_kf * 8] =
                make_uint4(f2tf32(f0.x), f2tf32(f0.y), f2tf32(f1.x), f2tf32(f1.y));
            *(uint4*)&As[cur][m * SA + a_kf * 8 + 4] =
                make_uint4(f2tf32(f2.x), f2tf32(f2.y), f2tf32(f3.x), f2tf32(f3.y));
        }
        #pragma unroll
        for (int it = 0; it < 4; it++) {
            int k = b_k0 + it * 8;
            *(uint4*)&Bs[cur][k * SB + b_nq * 4] =
                make_uint4(f2tf32(br[it].x), f2tf32(br[it].y),
                           f2tf32(br[it].z), f2tf32(br[it].w));
        }
        __syncthreads();

        if (k0 < 7) {
            int kb = (k0 + 1) * 32;
            #pragma unroll
            for (int it = 0; it < 2; it++) {
                int gr = bm + a_m0 + it * 32;
                ar[it] = (gr < M) ? *(const uint4*)&g_Hh[(size_t)gr * 256 + kb + a_kf * 8]
                                  : make_uint4(0, 0, 0, 0);
            }
            #pragma unroll
            for (int it = 0; it < 4; it++)
                br[it] = *(const float4*)&B[(size_t)(kb + b_k0 + it * 8) * N + bn + b_nq * 4];
        }

        gemm_compute(As[cur], Bs[cur], wm, wn, lane, acc);
        __syncthreads();
    }

    gemm_epilogue(g_Y1h, M, N, bm, bn, wm, wn, lane, acc);
}

// ---------------- bucket SpMMs (R8-proven, warp per row, 2-edge unroll) ----------------
__device__ __forceinline__ void fma_h8(float* a, uint4 r, float v) {
    float2 f0 = __half22float2(*(__half2*)&r.x);
    float2 f1 = __half22float2(*(__half2*)&r.y);
    float2 f2 = __half22float2(*(__half2*)&r.z);
    float2 f3 = __half22float2(*(__half2*)&r.w);
    a[0] = fmaf(v, f0.x, a[0]); a[1] = fmaf(v, f0.y, a[1]);
    a[2] = fmaf(v, f1.x, a[2]); a[3] = fmaf(v, f1.y, a[3]);
    a[4] = fmaf(v, f2.x, a[4]); a[5] = fmaf(v, f2.y, a[5]);
    a[6] = fmaf(v, f3.x, a[6]); a[7] = fmaf(v, f3.y, a[7]);
}

// g_Hh = fp16(relu(A @ Y0h)): each lane covers cols [lane*8, lane*8+8)
__global__ void spmm1_kernel() {
    int row = blockIdx.x * (blockDim.x >> 5) + (threadIdx.x >> 5);
    if (row >= N_NODES) return;
    int lane = threadIdx.x & 31;
    int deg = g_cnt[row];
    if (deg > CAP) deg = CAP;
    const int2* bk = g_bucket + row * CAP;

    float acc[8] = {};
    int e = 0;
    for (; e + 2 <= deg; e += 2) {
        int2 t0 = bk[e], t1 = bk[e + 1];
        uint4 r0 = *(const uint4*)(g_Y0h + (size_t)t0.x * HIDDEN + lane * 8);
        uint4 r1 = *(const uint4*)(g_Y0h + (size_t)t1.x * HIDDEN + lane * 8);
        fma_h8(acc, r0, __int_as_float(t0.y));
        fma_h8(acc, r1, __int_as_float(t1.y));
    }
    if (e < deg) {
        int2 t0 = bk[e];
        uint4 r0 = *(const uint4*)(g_Y0h + (size_t)t0.x * HIDDEN + lane * 8);
        fma_h8(acc, r0, __int_as_float(t0.y));
    }

    #pragma unroll
    for (int i = 0; i < 8; i++) acc[i] = fmaxf(acc[i], 0.f);
    __half2 h0 = __floats2half2_rn(acc[0], acc[1]);
    __half2 h1 = __floats2half2_rn(acc[2], acc[3]);
    __half2 h2 = __floats2half2_rn(acc[4], acc[5]);
    __half2 h3 = __floats2half2_rn(acc[6], acc[7]);
    *(uint4*)&g_Hh[(size_t)row * HIDDEN + lane * 8] =
        make_uint4(*(uint32_t*)&h0, *(uint32_t*)&h1, *(uint32_t*)&h2, *(uint32_t*)&h3);
}

// out = A @ Y1h: each lane covers cols [lane*4, lane*4+4). Zero-restores g_cnt.
__global__ void spmm2_kernel(float4* __restrict__ out) {
    int row = blockIdx.x * (blockDim.x >> 5) + (threadIdx.x >> 5);
    if (row >= N_NODES) return;
    int lane = threadIdx.x & 31;
    int deg = g_cnt[row];
    if (deg > CAP) deg = CAP;
    const int2* bk = g_bucket + row * CAP;

    float acc[4] = {};
    int e = 0;
    for (; e + 2 <= deg; e += 2) {
        int2 t0 = bk[e], t1 = bk[e + 1];
        uint2 r0 = *(const uint2*)(g_Y1h + (size_t)t0.x * OUT_DIM + lane * 4);
        uint2 r1 = *(const uint2*)(g_Y1h + (size_t)t1.x * OUT_DIM + lane * 4);
        float v0 = __int_as_float(t0.y), v1 = __int_as_float(t1.y);
        float2 a0 = __half22float2(*(__half2*)&r0.x);
        float2 a1 = __half22float2(*(__half2*)&r0.y);
        float2 b0 = __half22float2(*(__half2*)&r1.x);
        float2 b1 = __half22float2(*(__half2*)&r1.y);
        acc[0] = fmaf(v0, a0.x, acc[0]); acc[1] = fmaf(v0, a0.y, acc[1]);
        acc[2] = fmaf(v0, a1.x, acc[2]); acc[3] = fmaf(v0, a1.y, acc[3]);
        acc[0] = fmaf(v1, b0.x, acc[0]); acc[1] = fmaf(v1, b0.y, acc[1]);
        acc[2] = fmaf(v1, b1.x, acc[2]); acc[3] = fmaf(v1, b1.y, acc[3]);
    }
    if (e < deg) {
        int2 t0 = bk[e];
        uint2 r0 = *(const uint2*)(g_Y1h + (size_t)t0.x * OUT_DIM + lane * 4);
        float v0 = __int_as_float(t0.y);
        float2 a0 = __half22float2(*(__half2*)&r0.x);
        float2 a1 = __half22float2(*(__half2*)&r0.y);
        acc[0] = fmaf(v0, a0.x, acc[0]); acc[1] = fmaf(v0, a0.y, acc[1]);
        acc[2] = fmaf(v0, a1.x, acc[2]); acc[3] = fmaf(v0, a1.y, acc[3]);
    }
    out[(size_t)row * 32 + lane] = make_float4(acc[0], acc[1], acc[2], acc[3]);

    if (lane == 0) g_cnt[row] = 0;   // restore invariant for next invocation
}

// ---------------- launch ----------------
extern "C" void kernel_launch(void* const* d_in, const int* in_sizes, int n_in,
                              void* d_out, int out_size) {
    const float* features = (const float*)d_in[0];
    const void*  edge_src = d_in[1];
    const void*  edge_dst = d_in[2];
    const float* edge_val = (const float*)d_in[3];
    const float* W0       = (const float*)d_in[4];
    const float* W1       = (const float*)d_in[5];
    float4*      out      = (float4*)d_out;

    static cudaStream_t s_side = nullptr;
    static cudaEvent_t  ev_fork = nullptr, ev_join = nullptr;
    if (s_side == nullptr) {
        cudaStreamCreateWithFlags(&s_side, cudaStreamNonBlocking);
        cudaEventCreateWithFlags(&ev_fork, cudaEventDisableTiming);
        cudaEventCreateWithFlags(&ev_join, cudaEventDisableTiming);
    }

    // Fork: GEMM1 on side branch (independent of edge bucketing)
    cudaEventRecord(ev_fork, 0);
    cudaStreamWaitEvent(s_side, ev_fork, 0);
    {
        dim3 grid(HIDDEN / 64, (N_NODES + 63) / 64);
        gemm_XW0_kernel<<<grid, 128, 0, s_side>>>(features, W0, N_NODES);
    }
    cudaEventRecord(ev_join, s_side);

    // Main branch: bucket the edges
    scatter_kernel<<<(N_EDGES + 255) / 256, 256>>>(edge_src, edge_dst, edge_val);

    // Join: SpMM1 needs both buckets and Y0h
    cudaStreamWaitEvent(0, ev_join, 0);

    // g_Hh = fp16(relu(A @ Y0h))
    spmm1_kernel<<<(N_NODES + 7) / 8, 256>>>();

    // Y1h = Hh @ W1
    {
        dim3 grid(OUT_DIM / 64, (N_NODES + 63) / 64);
        gemm_HW1_kernel<<<grid, 128>>>(W1, N_NODES);
    }

    // out = A @ Y1h  (also zero-restores g_cnt)
    spmm2_kernel<<<(N_NODES + 7) / 8, 256>>>(out);
}